// round 3
// baseline (speedup 1.0000x reference)
#include <cuda_runtime.h>

#define N 8192
#define THREADS 256
#define ROWS_PER_WARP 2
#define WARPS 8
#define ROWS_PER_BLOCK (WARPS * ROWS_PER_WARP)   // 16
#define GRID (N / ROWS_PER_BLOCK)                // 512
#define ITERS (N / (32 * 4))                     // 64 float4 iters per lane per row

__device__ float g_r[N];   // tanh(y), computed once

__global__ void tanh_kernel(const float* __restrict__ y)
{
    int i = blockIdx.x * blockDim.x + threadIdx.x;
    g_r[i] = tanhf(y[i]);
}

__global__ __launch_bounds__(THREADS, 4) void gemv_kernel(
    const float* __restrict__ x,
    const float* __restrict__ y,
    const float* __restrict__ W,
    float* __restrict__ out)
{
    __shared__ float r_s[N];  // 32 KB, staged once

    const int tid  = threadIdx.x;
    const int warp = tid >> 5;
    const int lane = tid & 31;

    // Stage r into shared (g_r is L2-resident after tanh_kernel).
    {
        const float4* rsrc = reinterpret_cast<const float4*>(g_r);
        float4* rdst = reinterpret_cast<float4*>(r_s);
        #pragma unroll
        for (int i = tid; i < N / 4; i += THREADS)
            rdst[i] = rsrc[i];
    }
    __syncthreads();

    const int row0 = blockIdx.x * ROWS_PER_BLOCK + warp * ROWS_PER_WARP;
    const int row1 = row0 + 1;

    const float4* __restrict__ W0 =
        reinterpret_cast<const float4*>(W + (size_t)row0 * N);
    const float4* __restrict__ W1 =
        reinterpret_cast<const float4*>(W + (size_t)row1 * N);
    const float4* rs4 = reinterpret_cast<const float4*>(r_s);

    // Per row: 2 independent accumulators; per step: 4 W loads in flight.
    float a00 = 0.f, a01 = 0.f;   // row0
    float a10 = 0.f, a11 = 0.f;   // row1

    #pragma unroll
    for (int i = 0; i < ITERS; i += 2) {
        // Batch all global loads first -> 4 outstanding LDG.128 per warp step.
        float4 w00 = W0[(i + 0) * 32 + lane];
        float4 w01 = W0[(i + 1) * 32 + lane];
        float4 w10 = W1[(i + 0) * 32 + lane];
        float4 w11 = W1[(i + 1) * 32 + lane];
        float4 v0  = rs4[(i + 0) * 32 + lane];
        float4 v1  = rs4[(i + 1) * 32 + lane];

        a00 += w00.x * v0.x + w00.y * v0.y + w00.z * v0.z + w00.w * v0.w;
        a01 += w01.x * v1.x + w01.y * v1.y + w01.z * v1.z + w01.w * v1.w;
        a10 += w10.x * v0.x + w10.y * v0.y + w10.z * v0.z + w10.w * v0.w;
        a11 += w11.x * v1.x + w11.y * v1.y + w11.z * v1.z + w11.w * v1.w;
    }

    float acc0 = a00 + a01;
    float acc1 = a10 + a11;

    #pragma unroll
    for (int off = 16; off > 0; off >>= 1) {
        acc0 += __shfl_xor_sync(0xFFFFFFFFu, acc0, off);
        acc1 += __shfl_xor_sync(0xFFFFFFFFu, acc1, off);
    }

    if (lane == 0) {
        const float DT  = 1e-3f;
        const float TAU = 1e-2f;
        float y0 = y[row0];
        float y1 = y[row1];
        out[row0] = y0 + DT * ((-y0 + acc0 + x[row0]) / TAU);
        out[row1] = y1 + DT * ((-y1 + acc1 + x[row1]) / TAU);
    }
}

extern "C" void kernel_launch(void* const* d_in, const int* in_sizes, int n_in,
                              void* d_out, int out_size)
{
    const float* x = (const float*)d_in[0];
    const float* y = (const float*)d_in[1];
    const float* W = (const float*)d_in[2];
    float* out = (float*)d_out;

    tanh_kernel<<<N / THREADS, THREADS>>>(y);
    gemv_kernel<<<GRID, THREADS>>>(x, y, W, out);
}

// round 4
// speedup vs baseline: 1.1649x; 1.1649x over previous
#include <cuda_runtime.h>

#define N 8192
#define THREADS 256
#define ROWS_PER_BLOCK 8
#define KCHUNK 2048
#define NCHUNK (N / KCHUNK)                 // 4
#define ROWGROUPS (N / ROWS_PER_BLOCK)      // 1024
#define GRID (ROWGROUPS * NCHUNK)           // 4096
#define ITERS (KCHUNK / (32 * 4))           // 16 float4 iters per lane

__device__ float g_part[NCHUNK * N];

__global__ __launch_bounds__(THREADS) void gemv_partial_kernel(
    const float* __restrict__ y,
    const float* __restrict__ W)
{
    __shared__ float r_s[KCHUNK];  // 8 KB

    const int tid   = threadIdx.x;
    const int bx    = blockIdx.x;
    const int chunk = bx >> 10;          // 0..3   (chunk-major: bx / ROWGROUPS)
    const int rowg  = bx & (ROWGROUPS - 1);
    const int col0  = chunk * KCHUNK;

    // Stage r-chunk: tanh computed inline (y chunk is L2-hot, tanh is cheap).
    {
        const float4* ysrc = reinterpret_cast<const float4*>(y + col0);
        float4* rdst = reinterpret_cast<float4*>(r_s);
        #pragma unroll
        for (int i = tid; i < KCHUNK / 4; i += THREADS) {
            float4 v = ysrc[i];
            float4 t;
            t.x = tanhf(v.x); t.y = tanhf(v.y);
            t.z = tanhf(v.z); t.w = tanhf(v.w);
            rdst[i] = t;
        }
    }
    __syncthreads();

    const int warp = tid >> 5;
    const int lane = tid & 31;
    const int row  = rowg * ROWS_PER_BLOCK + warp;

    const float4* __restrict__ Wrow =
        reinterpret_cast<const float4*>(W + (size_t)row * N + col0);
    const float4* rs4 = reinterpret_cast<const float4*>(r_s);

    float a0 = 0.f, a1 = 0.f, a2 = 0.f, a3 = 0.f;
    #pragma unroll
    for (int i = 0; i < ITERS; i += 4) {
        float4 w0 = Wrow[(i + 0) * 32 + lane];
        float4 w1 = Wrow[(i + 1) * 32 + lane];
        float4 w2 = Wrow[(i + 2) * 32 + lane];
        float4 w3 = Wrow[(i + 3) * 32 + lane];
        float4 v0 = rs4[(i + 0) * 32 + lane];
        float4 v1 = rs4[(i + 1) * 32 + lane];
        float4 v2 = rs4[(i + 2) * 32 + lane];
        float4 v3 = rs4[(i + 3) * 32 + lane];
        a0 += w0.x * v0.x + w0.y * v0.y + w0.z * v0.z + w0.w * v0.w;
        a1 += w1.x * v1.x + w1.y * v1.y + w1.z * v1.z + w1.w * v1.w;
        a2 += w2.x * v2.x + w2.y * v2.y + w2.z * v2.z + w2.w * v2.w;
        a3 += w3.x * v3.x + w3.y * v3.y + w3.z * v3.z + w3.w * v3.w;
    }
    float acc = (a0 + a1) + (a2 + a3);

    #pragma unroll
    for (int off = 16; off > 0; off >>= 1)
        acc += __shfl_xor_sync(0xFFFFFFFFu, acc, off);

    if (lane == 0)
        g_part[chunk * N + row] = acc;
}

__global__ void epilogue_kernel(
    const float* __restrict__ x,
    const float* __restrict__ y,
    float* __restrict__ out)
{
    int i = blockIdx.x * blockDim.x + threadIdx.x;
    float acc = g_part[0 * N + i] + g_part[1 * N + i]
              + g_part[2 * N + i] + g_part[3 * N + i];
    const float DT  = 1e-3f;
    const float TAU = 1e-2f;
    float yi = y[i];
    out[i] = yi + DT * ((-yi + acc + x[i]) / TAU);
}

extern "C" void kernel_launch(void* const* d_in, const int* in_sizes, int n_in,
                              void* d_out, int out_size)
{
    const float* x = (const float*)d_in[0];
    const float* y = (const float*)d_in[1];
    const float* W = (const float*)d_in[2];
    float* out = (float*)d_out;

    gemv_partial_kernel<<<GRID, THREADS>>>(y, W);
    epilogue_kernel<<<N / THREADS, THREADS>>>(x, y, out);
}